// round 2
// baseline (speedup 1.0000x reference)
#include <cuda_runtime.h>
#include <math.h>

// Problem constants
#define BN 4
#define HH 96
#define WW 96
#define NN (HH*WW)        // 9216
#define EH (HH*(WW-1))    // 9120 horizontal edges
#define EV ((HH-1)*WW)    // 9120 vertical edges
#define EE (EH+EV)        // 18240
#define NCH 21            // pred channels
#define CF  22            // channels incl. norm channel
#define CLOW 3
#define CHIGH 512

// ---------------- device scratch (static, no allocation) ----------------
__device__ float  g_prob [BN*NCH*NN];
__device__ float  g_AS1  [BN*NCH*NN];
__device__ float  g_AS2  [BN*NCH*NN];
__device__ double g_wedge[2][BN*EE];       // MST edge weights (double, matches ref f64)
__device__ int    g_mst  [2][BN*EE];       // MST membership flags
__device__ int    g_adj  [2][BN*NN*4];     // tree adjacency (-1 = none)
__device__ int    g_parent[2][BN*NN];      // parent (root = -1)
__device__ int    g_order [2][BN*NN];      // BFS order
__device__ int    g_lvloff[2][BN*(NN+2)];  // level offsets
__device__ int    g_nlev  [2][BN];
__device__ float  g_wnode [2][BN*NN];      // per-node parent-edge weight
// Boruvka scratch (shared between the two sequential tree builds)
__device__ int    g_comp[BN*NN];
__device__ unsigned long long g_bw[BN*NN];
__device__ int    g_be[BN*NN];
__device__ int    g_lk[BN*NN];
// DP scratch (shared between the two sequential filters)
__device__ float  g_a[BN*NN*CF];
__device__ float  g_s[BN*NN*CF];
// loss accumulators: [0]=loss, [1]=n
__device__ double g_acc[2];

__device__ __forceinline__ void edge_ep(int e, int& a, int& b) {
    if (e < EH) { int r = e / (WW-1), c = e % (WW-1); a = r*WW + c; b = a + 1; }
    else        { int j = e - EH;                      a = j;        b = j + WW; }
}

// ---------------- kernels ----------------

__global__ void k_sigmoid(const float* __restrict__ preds) {
    int i = blockIdx.x*blockDim.x + threadIdx.x;
    if (i < BN*NCH*NN) g_prob[i] = 1.0f / (1.0f + expf(-preds[i]));
}

// edge weights in double: sum over channels of (f[a]-f[b])^2
__global__ void k_edgew(const float* __restrict__ feat, int C, int tree) {
    int i = blockIdx.x*blockDim.x + threadIdx.x;
    if (i >= BN*EE) return;
    int b = i / EE, e = i % EE;
    int a, bb; edge_ep(e, a, bb);
    const float* f = feat + (size_t)b * C * NN;
    double s = 0.0;
    for (int c = 0; c < C; c++) {
        double d = (double)f[c*NN + a] - (double)f[c*NN + bb];
        s += d * d;
    }
    g_wedge[tree][i] = s;
}

// Boruvka MST, one block per batch. Unique MST under distinct weights;
// (weight,edge-index) lexicographic selection => only 2-cycles in hooking.
__global__ __launch_bounds__(1024) void k_boruvka(int tree) {
    int b = blockIdx.x, tid = threadIdx.x, T = blockDim.x;
    const double* w = g_wedge[tree] + b*EE;
    int* mf = g_mst[tree] + b*EE;
    int* cp = g_comp + b*NN;
    unsigned long long* bw = g_bw + b*NN;
    int* be = g_be + b*NN;
    int* lk = g_lk + b*NN;

    for (int v = tid; v < NN; v += T) cp[v] = v;
    for (int e = tid; e < EE; e += T) mf[e] = 0;
    __syncthreads();

    __shared__ int s_any, s_chg;
    for (int round = 0; round < 14; round++) {
        for (int v = tid; v < NN; v += T) {
            bw[v] = 0xFFFFFFFFFFFFFFFFull;
            be[v] = 0x7FFFFFFF;
            lk[v] = v;
        }
        if (tid == 0) s_any = 0;
        __syncthreads();

        // phase 1: per-component min weight
        for (int e = tid; e < EE; e += T) {
            int a, bb; edge_ep(e, a, bb);
            int ca = cp[a], cb = cp[bb];
            if (ca != cb) {
                unsigned long long k = (unsigned long long)__double_as_longlong(w[e]);
                atomicMin(&bw[ca], k);
                atomicMin(&bw[cb], k);
                s_any = 1;
            }
        }
        __syncthreads();
        if (!s_any) break;

        // phase 2: min edge index among min-weight edges
        for (int e = tid; e < EE; e += T) {
            int a, bb; edge_ep(e, a, bb);
            int ca = cp[a], cb = cp[bb];
            if (ca != cb) {
                unsigned long long k = (unsigned long long)__double_as_longlong(w[e]);
                if (k == bw[ca]) atomicMin(&be[ca], e);
                if (k == bw[cb]) atomicMin(&be[cb], e);
            }
        }
        __syncthreads();

        // hooking
        for (int v = tid; v < NN; v += T) {
            if (cp[v] == v && be[v] != 0x7FFFFFFF) {
                int e = be[v]; int a, bb; edge_ep(e, a, bb);
                int ca = cp[a], cb = cp[bb];
                lk[v] = (ca == v) ? cb : ca;
                mf[e] = 1;
            }
        }
        __syncthreads();

        // break mutual 2-cycles (smaller id becomes root)
        for (int v = tid; v < NN; v += T) {
            int o = lk[v];
            if (o != v && lk[o] == v && v < o) lk[v] = v;
        }
        __syncthreads();

        // pointer jumping until converged
        for (int it = 0; it < 20; it++) {
            if (tid == 0) s_chg = 0;
            __syncthreads();
            for (int v = tid; v < NN; v += T) {
                int l = lk[v]; int ll = lk[l];
                if (l != ll) { lk[v] = ll; s_chg = 1; }
            }
            __syncthreads();
            if (!s_chg) break;
        }
        for (int v = tid; v < NN; v += T) cp[v] = lk[cp[v]];
        __syncthreads();
    }
}

// Build tree adjacency + BFS rooting from node 0. One block per batch.
__global__ __launch_bounds__(256) void k_bfs(int tree) {
    int b = blockIdx.x, tid = threadIdx.x, T = blockDim.x;
    const int* mf = g_mst[tree] + b*EE;
    int* adj = g_adj[tree] + b*NN*4;
    int* par = g_parent[tree] + b*NN;
    int* ord = g_order[tree] + b*NN;
    int* lvl = g_lvloff[tree] + b*(NN+2);

    for (int v = tid; v < NN; v += T) {
        int r = v / WW, c = v % WW;
        int n0 = -1, n1 = -1, n2 = -1, n3 = -1;
        if (c > 0      && mf[r*(WW-1) + c - 1])   n0 = v - 1;
        if (c < WW-1   && mf[r*(WW-1) + c])       n1 = v + 1;
        if (r > 0      && mf[EH + (r-1)*WW + c])  n2 = v - WW;
        if (r < HH-1   && mf[EH + r*WW + c])      n3 = v + WW;
        adj[v*4+0] = n0; adj[v*4+1] = n1; adj[v*4+2] = n2; adj[v*4+3] = n3;
    }
    __shared__ int s_cnt;
    if (tid == 0) { ord[0] = 0; par[0] = -1; lvl[0] = 0; lvl[1] = 1; }
    __syncthreads();

    int cur = 0, end = 1, d = 0;
    while (true) {
        if (tid == 0) s_cnt = 0;
        __syncthreads();
        for (int i = cur + tid; i < end; i += T) {
            int u = ord[i]; int pu = par[u];
            #pragma unroll
            for (int k = 0; k < 4; k++) {
                int nb = adj[u*4+k];
                if (nb >= 0 && nb != pu) {
                    int pos = end + atomicAdd(&s_cnt, 1);
                    ord[pos] = nb;
                    par[nb] = u;
                }
            }
        }
        __syncthreads();
        int cnt = s_cnt;
        if (tid == 0) lvl[d+2] = end + cnt;
        if (cnt == 0) { if (tid == 0) g_nlev[tree][b] = d + 1; break; }
        cur = end; end += cnt; d++;
        __syncthreads();
    }
}

// per-node parent edge weight w = exp(-||e_v - e_par||^2 / sigma), root -> 0
__global__ void k_nodew(const float* __restrict__ feat, int C, float sigma, int tree) {
    int i = blockIdx.x*blockDim.x + threadIdx.x;
    if (i >= BN*NN) return;
    int b = i / NN, v = i % NN;
    int p = g_parent[tree][i];
    float wv = 0.0f;
    if (p >= 0) {
        const float* f = feat + (size_t)b * C * NN;
        float ss = 0.0f;
        for (int c = 0; c < C; c++) {
            float d = f[c*NN + v] - f[c*NN + p];
            ss += d * d;
        }
        wv = expf(-ss / sigma);
    }
    g_wnode[tree][i] = wv;
}

// Two-pass tree DP (22 channels incl. norm), one block per batch.
// stage 0: g_prob -> (tree 0) -> g_AS1 ; stage 1: g_AS1 -> (tree 1) -> g_AS2.
// NOTE: device globals are resolved ON DEVICE (never passed from host: the
// host-side symbol address is a host shadow, not the device address).
__global__ __launch_bounds__(1024) void k_treedp(int stage) {
    const int tree = stage;
    const float* feat = (stage == 0) ? g_prob : g_AS1;
    float* out = (stage == 0) ? g_AS1 : g_AS2;

    int b = blockIdx.x, tid = threadIdx.x, T = blockDim.x;
    const int* adj = g_adj[tree] + b*NN*4;
    const int* par = g_parent[tree] + b*NN;
    const int* ord = g_order[tree] + b*NN;
    const int* lvl = g_lvloff[tree] + b*(NN+2);
    const float* wn = g_wnode[tree] + b*NN;
    float* a = g_a + (size_t)b*NN*CF;
    float* s = g_s + (size_t)b*NN*CF;
    const float* fb = feat + (size_t)b*NCH*NN;
    float* ob = out + (size_t)b*NCH*NN;
    int D = g_nlev[tree][b];

    // up pass: children (deeper levels) before parents
    for (int d = D - 1; d >= 0; d--) {
        int lo = lvl[d], hi = lvl[d+1], m = (hi - lo) * CF;
        for (int t = tid; t < m; t += T) {
            int u = ord[lo + t / CF];
            int c = t % CF;
            float acc = (c < NCH) ? fb[c*NN + u] : 1.0f;
            int pu = par[u];
            #pragma unroll
            for (int k = 0; k < 4; k++) {
                int nb = adj[u*4+k];
                if (nb >= 0 && nb != pu) acc += wn[nb] * a[nb*CF + c];
            }
            a[u*CF + c] = acc;
        }
        __syncthreads();
    }
    // down pass: parents before children
    for (int d = 0; d < D; d++) {
        int lo = lvl[d], hi = lvl[d+1], m = (hi - lo) * CF;
        for (int t = tid; t < m; t += T) {
            int u = ord[lo + t / CF];
            int c = t % CF;
            float av = a[u*CF + c];
            int pu = par[u];
            float sv;
            if (pu < 0) sv = av;
            else {
                float wu = wn[u];
                sv = av + wu * (s[pu*CF + c] - wu * av);
            }
            s[u*CF + c] = sv;
        }
        __syncthreads();
    }
    // normalize + write
    for (int t = tid; t < NCH*NN; t += T) {
        int c = t / NN, v = t % NN;
        ob[c*NN + v] = s[v*CF + c] / s[v*CF + NCH];
    }
}

__global__ void k_zero_acc() { g_acc[0] = 0.0; g_acc[1] = 0.0; }

__global__ __launch_bounds__(256) void k_loss(const float* __restrict__ roi) {
    double lsum = 0.0, nsum = 0.0;
    int stride = gridDim.x * blockDim.x;
    for (int idx = blockIdx.x*blockDim.x + threadIdx.x; idx < BN*NCH*NN; idx += stride) {
        int v = idx % NN;
        int bc = idx / NN;
        int c = bc % NCH, b = bc / NCH;
        int h = v / WW, wd = v % WW;
        float r = roi[b*(2*HH)*(2*WW) + (2*h)*(2*WW) + 2*wd];
        lsum += (double)(r * fabsf(g_prob[idx] - g_AS2[idx]));
        if (c == 0) nsum += (double)r;
    }
    __shared__ double shl[256], shn[256];
    int tid = threadIdx.x;
    shl[tid] = lsum; shn[tid] = nsum;
    __syncthreads();
    for (int off = 128; off > 0; off >>= 1) {
        if (tid < off) { shl[tid] += shl[tid+off]; shn[tid] += shn[tid+off]; }
        __syncthreads();
    }
    if (tid == 0) {
        atomicAdd(&g_acc[0], shl[0]);
        atomicAdd(&g_acc[1], shn[0]);
    }
}

__global__ void k_write(float* out) {
    double n = g_acc[1];
    out[0] = (n > 0.0) ? (float)(g_acc[0] / n) : 0.0f;
}

// ---------------- launch ----------------
extern "C" void kernel_launch(void* const* d_in, const int* in_sizes, int n_in,
                              void* d_out, int out_size) {
    const float *preds = nullptr, *lowf = nullptr, *highf = nullptr, *roi = nullptr;
    for (int i = 0; i < n_in; i++) {
        switch (in_sizes[i]) {
            case BN*NCH*NN:        preds = (const float*)d_in[i]; break;   // 774144
            case BN*CLOW*NN:       lowf  = (const float*)d_in[i]; break;   // 110592
            case BN*CHIGH*NN:      highf = (const float*)d_in[i]; break;   // 18874368
            case BN*(2*HH)*(2*WW): roi   = (const float*)d_in[i]; break;   // 147456
        }
    }
    float* out = (float*)d_out;

    k_sigmoid<<<(BN*NCH*NN + 255)/256, 256>>>(preds);

    k_edgew<<<(BN*EE + 127)/128, 128>>>(lowf,  CLOW,  0);
    k_edgew<<<(BN*EE + 127)/128, 128>>>(highf, CHIGH, 1);

    k_boruvka<<<BN, 1024>>>(0);
    k_boruvka<<<BN, 1024>>>(1);

    k_bfs<<<BN, 256>>>(0);
    k_bfs<<<BN, 256>>>(1);

    k_nodew<<<(BN*NN + 127)/128, 128>>>(lowf,  CLOW,  0.02f, 0);
    k_nodew<<<(BN*NN + 127)/128, 128>>>(highf, CHIGH, 1.0f,  1);

    k_treedp<<<BN, 1024>>>(0);
    k_treedp<<<BN, 1024>>>(1);

    k_zero_acc<<<1, 1>>>();
    k_loss<<<1024, 256>>>(roi);
    k_write<<<1, 1>>>(out);
    (void)out_size;
}

// round 3
// speedup vs baseline: 1.0526x; 1.0526x over previous
#include <cuda_runtime.h>
#include <math.h>

// Problem constants
#define BN 4
#define HH 96
#define WW 96
#define NN (HH*WW)        // 9216
#define EH (HH*(WW-1))    // 9120
#define EV ((HH-1)*WW)    // 9120
#define EE (EH+EV)        // 18240
#define NCH 21
#define CF  22
#define CLOW 3
#define CHIGH 512

// ---------------- device scratch ----------------
__device__ float  g_prob [BN*NCH*NN];
__device__ float  g_AS2  [BN*NCH*NN];
__device__ double g_wedge[2][BN*EE];
__device__ int    g_mst  [2][BN*EE];
__device__ int    g_adj  [2][BN*NN*4];
__device__ int    g_parent[2][BN*NN];
__device__ int    g_order [2][BN*NN];
__device__ int    g_pos   [2][BN*NN];     // node -> BFS position
__device__ int    g_lvloff[2][BN*(NN+2)];
__device__ int    g_nlev  [2][BN];
__device__ float  g_wnode [2][BN*NN];
// packed per-position records (BFS order)
__device__ int4   g_rec1[2][BN*NN];       // {u, parent_pos, cpos0, cpos1}
__device__ int4   g_rec2[2][BN*NN];       // {cpos2, cpos3, bits(w_u), 0}
__device__ float4 g_recw[2][BN*NN];       // child weights
// position-ordered features for each stage
__device__ float  g_fp0[BN*NN*CF];
__device__ float  g_fp1[BN*NN*CF];
// DP scratch
__device__ float  g_a[BN*NN*CF];
__device__ float  g_s[BN*NN*CF];
__device__ double g_acc[2];

__device__ __forceinline__ void edge_ep(int e, int& a, int& b) {
    if (e < EH) { int r = e / (WW-1), c = e % (WW-1); a = r*WW + c; b = a + 1; }
    else        { int j = e - EH;                      a = j;        b = j + WW; }
}

// ---------------- kernels ----------------

__global__ void k_sigmoid(const float* __restrict__ preds) {
    int i = blockIdx.x*blockDim.x + threadIdx.x;
    if (i < BN*NCH*NN) g_prob[i] = 1.0f / (1.0f + expf(-preds[i]));
}

// low tree: exact double (C=3, trivial FP64 cost)
__global__ void k_edgew_low(const float* __restrict__ feat) {
    int i = blockIdx.x*blockDim.x + threadIdx.x;
    if (i >= BN*EE) return;
    int b = i / EE, e = i % EE;
    int a, bb; edge_ep(e, a, bb);
    const float* f = feat + (size_t)b * CLOW * NN;
    double s = 0.0;
    #pragma unroll
    for (int c = 0; c < CLOW; c++) {
        double d = (double)f[c*NN + a] - (double)f[c*NN + bb];
        s += d * d;
    }
    g_wedge[0][i] = s;
}

// high tree: fp32 products + double-single (TwoSum) accumulation, no FP64 pipe.
// abs error ~1e-8 << typical adjacent weight gap ~1e-5 => identical argsort/MST.
__device__ __forceinline__ void twosum(float& s, float& comp, float p) {
    float t = s + p;
    float z = t - s;
    float e = (s - (t - z)) + (p - z);
    s = t; comp += e;
}
__global__ void k_edgew_high(const float* __restrict__ feat) {
    int i = blockIdx.x*blockDim.x + threadIdx.x;
    if (i >= BN*EE) return;
    int b = i / EE, e = i % EE;
    int a, bb; edge_ep(e, a, bb);
    const float* f = feat + (size_t)b * CHIGH * NN;
    float s0 = 0.f, c0 = 0.f, s1 = 0.f, c1 = 0.f;
    #pragma unroll 4
    for (int c = 0; c < CHIGH; c += 2) {
        float d0 = f[c*NN + a] - f[c*NN + bb];
        twosum(s0, c0, d0*d0);
        float d1 = f[(c+1)*NN + a] - f[(c+1)*NN + bb];
        twosum(s1, c1, d1*d1);
    }
    g_wedge[1][i] = ((double)s0 + (double)s1) + ((double)c0 + (double)c1);
}

// Boruvka MST, one block per (tree,batch), all scratch in shared memory.
#define SMEM_BORUVKA (NN*(8+4+4+4))
__global__ __launch_bounds__(1024) void k_boruvka_both() {
    int b = blockIdx.x & 3, tree = blockIdx.x >> 2;
    int tid = threadIdx.x, T = blockDim.x;
    const double* w = g_wedge[tree] + b*EE;
    int* mf = g_mst[tree] + b*EE;

    extern __shared__ char smraw[];
    unsigned long long* bw = (unsigned long long*)smraw;     // NN*8
    int* cp = (int*)(smraw + NN*8);                           // NN*4
    int* be = cp + NN;                                        // NN*4
    int* lk = be + NN;                                        // NN*4

    for (int v = tid; v < NN; v += T) cp[v] = v;
    for (int e = tid; e < EE; e += T) mf[e] = 0;
    __syncthreads();

    __shared__ int s_any, s_chg;
    for (int round = 0; round < 14; round++) {
        for (int v = tid; v < NN; v += T) {
            bw[v] = 0xFFFFFFFFFFFFFFFFull;
            be[v] = 0x7FFFFFFF;
            lk[v] = v;
        }
        if (tid == 0) s_any = 0;
        __syncthreads();

        for (int e = tid; e < EE; e += T) {
            int a, bb; edge_ep(e, a, bb);
            int ca = cp[a], cb = cp[bb];
            if (ca != cb) {
                unsigned long long k = (unsigned long long)__double_as_longlong(w[e]);
                atomicMin(&bw[ca], k);
                atomicMin(&bw[cb], k);
                s_any = 1;
            }
        }
        __syncthreads();
        if (!s_any) break;

        for (int e = tid; e < EE; e += T) {
            int a, bb; edge_ep(e, a, bb);
            int ca = cp[a], cb = cp[bb];
            if (ca != cb) {
                unsigned long long k = (unsigned long long)__double_as_longlong(w[e]);
                if (k == bw[ca]) atomicMin(&be[ca], e);
                if (k == bw[cb]) atomicMin(&be[cb], e);
            }
        }
        __syncthreads();

        for (int v = tid; v < NN; v += T) {
            if (cp[v] == v && be[v] != 0x7FFFFFFF) {
                int e = be[v]; int a, bb; edge_ep(e, a, bb);
                int ca = cp[a], cb = cp[bb];
                lk[v] = (ca == v) ? cb : ca;
                mf[e] = 1;
            }
        }
        __syncthreads();

        for (int v = tid; v < NN; v += T) {
            int o = lk[v];
            if (o != v && lk[o] == v && v < o) lk[v] = v;
        }
        __syncthreads();

        for (int it = 0; it < 20; it++) {
            if (tid == 0) s_chg = 0;
            __syncthreads();
            for (int v = tid; v < NN; v += T) {
                int l = lk[v]; int ll = lk[l];
                if (l != ll) { lk[v] = ll; s_chg = 1; }
            }
            __syncthreads();
            if (!s_chg) break;
        }
        for (int v = tid; v < NN; v += T) cp[v] = lk[cp[v]];
        __syncthreads();
    }
}

// adjacency build + BFS rooting from node 0, both trees concurrently.
__global__ __launch_bounds__(256) void k_bfs_both() {
    int b = blockIdx.x & 3, tree = blockIdx.x >> 2;
    int tid = threadIdx.x, T = blockDim.x;
    const int* mf = g_mst[tree] + b*EE;
    int* adj = g_adj[tree] + b*NN*4;
    int* par = g_parent[tree] + b*NN;
    int* ord = g_order[tree] + b*NN;
    int* lvl = g_lvloff[tree] + b*(NN+2);

    for (int v = tid; v < NN; v += T) {
        int r = v / WW, c = v % WW;
        int n0 = -1, n1 = -1, n2 = -1, n3 = -1;
        if (c > 0      && mf[r*(WW-1) + c - 1])   n0 = v - 1;
        if (c < WW-1   && mf[r*(WW-1) + c])       n1 = v + 1;
        if (r > 0      && mf[EH + (r-1)*WW + c])  n2 = v - WW;
        if (r < HH-1   && mf[EH + r*WW + c])      n3 = v + WW;
        adj[v*4+0] = n0; adj[v*4+1] = n1; adj[v*4+2] = n2; adj[v*4+3] = n3;
    }
    __shared__ int s_cnt;
    if (tid == 0) { ord[0] = 0; par[0] = -1; lvl[0] = 0; lvl[1] = 1; }
    __syncthreads();

    int cur = 0, end = 1, d = 0;
    while (true) {
        if (tid == 0) s_cnt = 0;
        __syncthreads();
        for (int i = cur + tid; i < end; i += T) {
            int u = ord[i]; int pu = par[u];
            #pragma unroll
            for (int k = 0; k < 4; k++) {
                int nb = adj[u*4+k];
                if (nb >= 0 && nb != pu) {
                    int p2 = end + atomicAdd(&s_cnt, 1);
                    ord[p2] = nb;
                    par[nb] = u;
                }
            }
        }
        __syncthreads();
        int cnt = s_cnt;
        if (tid == 0) lvl[d+2] = end + cnt;
        if (cnt == 0) { if (tid == 0) g_nlev[tree][b] = d + 1; break; }
        cur = end; end += cnt; d++;
        __syncthreads();
    }
}

__global__ void k_nodew(const float* __restrict__ feat, int C, float sigma, int tree) {
    int i = blockIdx.x*blockDim.x + threadIdx.x;
    if (i >= BN*NN) return;
    int b = i / NN, v = i % NN;
    int p = g_parent[tree][i];
    float wv = 0.0f;
    if (p >= 0) {
        const float* f = feat + (size_t)b * C * NN;
        float ss = 0.0f;
        #pragma unroll 4
        for (int c = 0; c < C; c++) {
            float d = f[c*NN + v] - f[c*NN + p];
            ss += d * d;
        }
        wv = expf(-ss / sigma);
    }
    g_wnode[tree][i] = wv;
}

// node -> BFS position
__global__ void k_invord() {
    int idx = blockIdx.x*blockDim.x + threadIdx.x;
    if (idx >= 2*BN*NN) return;
    int tree = idx / (BN*NN), r = idx % (BN*NN);
    g_pos[tree][(r/NN)*NN + g_order[tree][r]] = r % NN + 0; // pos within batch
}

// build packed per-position records
__global__ void k_pack() {
    int idx = blockIdx.x*blockDim.x + threadIdx.x;
    if (idx >= 2*BN*NN) return;
    int tree = idx / (BN*NN), r = idx % (BN*NN);
    int b = r / NN, i = r % NN;
    int u = g_order[tree][b*NN + i];
    int pu = g_parent[tree][b*NN + u];
    int ppos = (pu >= 0) ? g_pos[tree][b*NN + pu] : -1;
    int cp0 = -1, cp1 = -1, cp2 = -1, cp3 = -1;
    float cw0 = 0.f, cw1 = 0.f, cw2 = 0.f, cw3 = 0.f;
    int nc = 0;
    #pragma unroll
    for (int k = 0; k < 4; k++) {
        int nb = g_adj[tree][(b*NN + u)*4 + k];
        if (nb >= 0 && nb != pu) {
            int cpos = g_pos[tree][b*NN + nb];
            float cw = g_wnode[tree][b*NN + nb];
            if (nc == 0) { cp0 = cpos; cw0 = cw; }
            else if (nc == 1) { cp1 = cpos; cw1 = cw; }
            else if (nc == 2) { cp2 = cpos; cw2 = cw; }
            else { cp3 = cpos; cw3 = cw; }
            nc++;
        }
    }
    float wu = g_wnode[tree][b*NN + u];
    g_rec1[tree][b*NN + i] = make_int4(u, ppos, cp0, cp1);
    g_rec2[tree][b*NN + i] = make_int4(cp2, cp3, __float_as_int(wu), 0);
    g_recw[tree][b*NN + i] = make_float4(cw0, cw1, cw2, cw3);
}

// permute prob into tree-0 BFS position order
__global__ void k_permute0() {
    int idx = blockIdx.x*blockDim.x + threadIdx.x;
    if (idx >= BN*NN) return;
    int b = idx / NN, i = idx % NN;
    int u = g_order[0][b*NN + i];
    const float* pb = g_prob + (size_t)b*NCH*NN;
    float* dst = g_fp0 + (size_t)(b*NN + i)*CF;
    #pragma unroll
    for (int c = 0; c < NCH; c++) dst[c] = pb[c*NN + u];
}

// Both tree-filter stages in one kernel; one block per batch.
__global__ __launch_bounds__(1024) void k_treedp_both() {
    int b = blockIdx.x, tid = threadIdx.x, T = blockDim.x;
    float* A = g_a + (size_t)b*NN*CF;
    float* S = g_s + (size_t)b*NN*CF;

    for (int st = 0; st < 2; st++) {
        const int tr = st;
        const int4*   rec1 = g_rec1[tr] + b*NN;
        const int4*   rec2 = g_rec2[tr] + b*NN;
        const float4* recw = g_recw[tr] + b*NN;
        const int*    lvl  = g_lvloff[tr] + b*(NN+2);
        const float*  FP   = (st == 0 ? g_fp0 : g_fp1) + (size_t)b*NN*CF;
        int D = g_nlev[tr][b];

        // up: children before parents
        for (int d = D - 1; d >= 0; d--) {
            int lo = lvl[d], m = (lvl[d+1] - lo) * CF;
            for (int t = tid; t < m; t += T) {
                int i = lo + t / CF;
                int c = t - (t / CF) * CF;
                int4 r1 = rec1[i]; int4 r2 = rec2[i]; float4 wv = recw[i];
                float acc = (c < NCH) ? FP[i*CF + c] : 1.0f;
                if (r1.z >= 0) acc += wv.x * A[r1.z*CF + c];
                if (r1.w >= 0) acc += wv.y * A[r1.w*CF + c];
                if (r2.x >= 0) acc += wv.z * A[r2.x*CF + c];
                if (r2.y >= 0) acc += wv.w * A[r2.y*CF + c];
                A[i*CF + c] = acc;
            }
            __syncthreads();
        }
        // down: parents before children
        for (int d = 0; d < D; d++) {
            int lo = lvl[d], m = (lvl[d+1] - lo) * CF;
            for (int t = tid; t < m; t += T) {
                int i = lo + t / CF;
                int c = t - (t / CF) * CF;
                int4 r1 = rec1[i];
                float av = A[i*CF + c];
                float sv;
                if (r1.y < 0) sv = av;
                else {
                    float wu = __int_as_float(rec2[i].z);
                    sv = av + wu * (S[r1.y*CF + c] - wu * av);
                }
                S[i*CF + c] = sv;
            }
            __syncthreads();
        }
        // normalize; stage0 writes into tree-1 position order, stage1 to AS2
        for (int t = tid; t < NN*NCH; t += T) {
            int i = t / NCH;
            int c = t - i*NCH;
            float v = S[i*CF + c] / S[i*CF + NCH];
            int u = rec1[i].x;
            if (st == 0) {
                int j = g_pos[1][b*NN + u];
                g_fp1[(size_t)(b*NN + j)*CF + c] = v;
            } else {
                g_AS2[(size_t)b*NCH*NN + c*NN + u] = v;
            }
        }
        __syncthreads();
    }
}

__global__ void k_zero_acc() { g_acc[0] = 0.0; g_acc[1] = 0.0; }

__global__ __launch_bounds__(256) void k_loss(const float* __restrict__ roi) {
    double lsum = 0.0, nsum = 0.0;
    int stride = gridDim.x * blockDim.x;
    for (int idx = blockIdx.x*blockDim.x + threadIdx.x; idx < BN*NCH*NN; idx += stride) {
        int v = idx % NN;
        int bc = idx / NN;
        int c = bc % NCH, b = bc / NCH;
        int h = v / WW, wd = v % WW;
        float r = roi[b*(2*HH)*(2*WW) + (2*h)*(2*WW) + 2*wd];
        lsum += (double)(r * fabsf(g_prob[idx] - g_AS2[idx]));
        if (c == 0) nsum += (double)r;
    }
    __shared__ double shl[256], shn[256];
    int tid = threadIdx.x;
    shl[tid] = lsum; shn[tid] = nsum;
    __syncthreads();
    for (int off = 128; off > 0; off >>= 1) {
        if (tid < off) { shl[tid] += shl[tid+off]; shn[tid] += shn[tid+off]; }
        __syncthreads();
    }
    if (tid == 0) {
        atomicAdd(&g_acc[0], shl[0]);
        atomicAdd(&g_acc[1], shn[0]);
    }
}

__global__ void k_write(float* out) {
    double n = g_acc[1];
    out[0] = (n > 0.0) ? (float)(g_acc[0] / n) : 0.0f;
}

// ---------------- launch ----------------
extern "C" void kernel_launch(void* const* d_in, const int* in_sizes, int n_in,
                              void* d_out, int out_size) {
    const float *preds = nullptr, *lowf = nullptr, *highf = nullptr, *roi = nullptr;
    for (int i = 0; i < n_in; i++) {
        switch (in_sizes[i]) {
            case BN*NCH*NN:        preds = (const float*)d_in[i]; break;
            case BN*CLOW*NN:       lowf  = (const float*)d_in[i]; break;
            case BN*CHIGH*NN:      highf = (const float*)d_in[i]; break;
            case BN*(2*HH)*(2*WW): roi   = (const float*)d_in[i]; break;
        }
    }
    float* out = (float*)d_out;

    cudaFuncSetAttribute(k_boruvka_both,
                         cudaFuncAttributeMaxDynamicSharedMemorySize, SMEM_BORUVKA);

    k_sigmoid<<<(BN*NCH*NN + 255)/256, 256>>>(preds);

    k_edgew_low <<<(BN*EE + 127)/128, 128>>>(lowf);
    k_edgew_high<<<(BN*EE + 127)/128, 128>>>(highf);

    k_boruvka_both<<<2*BN, 1024, SMEM_BORUVKA>>>();
    k_bfs_both<<<2*BN, 256>>>();

    k_nodew<<<(BN*NN + 127)/128, 128>>>(lowf,  CLOW,  0.02f, 0);
    k_nodew<<<(BN*NN + 127)/128, 128>>>(highf, CHIGH, 1.0f,  1);

    k_invord  <<<(2*BN*NN + 255)/256, 256>>>();
    k_pack    <<<(2*BN*NN + 255)/256, 256>>>();
    k_permute0<<<(BN*NN + 255)/256, 256>>>();

    k_treedp_both<<<BN, 1024>>>();

    k_zero_acc<<<1, 1>>>();
    k_loss<<<1024, 256>>>(roi);
    k_write<<<1, 1>>>(out);
    (void)out_size;
}

// round 4
// speedup vs baseline: 1.7381x; 1.6513x over previous
#include <cuda_runtime.h>
#include <math.h>

#define BN 4
#define HH 96
#define WW 96
#define NN (HH*WW)        // 9216
#define EH (HH*(WW-1))    // 9120
#define EV ((HH-1)*WW)    // 9120
#define EE (EH+EV)        // 18240
#define NCH 21
#define CLOW 3
#define CHIGH 512
#define NGROUP 6          // channel groups for DP (4 real + norm each; last has 1)
#define DP_T 512
#define DP_SMEM ((5*NN + NN) * 4)          // A(5ch) + wpos  = 221184 B
#define BFS_SMEM (NN + NN*4 + NN*4)        // flags + ord + par = 82944 B
#define SMEM_BORUVKA (NN*(8+4+4+4))        // 184320 B

// ---------------- device scratch ----------------
__device__ float  g_prob[BN*NCH*NN];
__device__ float  g_AS2 [BN*NCH*NN];
__device__ float  g_hft [(size_t)BN*NN*CHIGH];  // high feats transposed [b][n][c]
__device__ double g_wedge[2][BN*EE];
__device__ int    g_mst [2][BN*EE];
__device__ int    g_ord [2][BN*NN];    // position -> node
__device__ int    g_par [2][BN*NN];    // node -> parent node (-1 root)
__device__ int    g_cs  [2][BN*NN];    // position -> first child position
__device__ int    g_cn  [2][BN*NN];    // position -> child count
__device__ int    g_pp  [2][BN*NN];    // position -> parent position (root->0)
__device__ float  g_wpos[2][BN*NN];    // position -> parent-edge weight (root 0)
__device__ int    g_lvl [2][BN*(NN+2)];
__device__ int    g_nlev[2][BN];
__device__ int    g_posN1[BN*NN];      // tree1: node -> position
__device__ int    g_perm01[BN*NN];     // tree0 pos -> tree1 pos
__device__ float  g_f0[BN*NCH*NN];     // stage0 features [b][c][pos0]
__device__ float  g_f1[BN*NCH*NN];     // stage1 features [b][c][pos1]
// boruvka scratch is in shared memory
__device__ double g_acc[2];

__device__ __forceinline__ void edge_ep(int e, int& a, int& b) {
    if (e < EH) { int r = e / (WW-1), c = e % (WW-1); a = r*WW + c; b = a + 1; }
    else        { int j = e - EH;                      a = j;        b = j + WW; }
}
__device__ __forceinline__ void twosum(float& s, float& comp, float p) {
    float t = s + p;
    float z = t - s;
    float e = (s - (t - z)) + (p - z);
    s = t; comp += e;
}

// ---------------- kernels ----------------

__global__ void k_sigmoid(const float* __restrict__ preds) {
    int i = blockIdx.x*blockDim.x + threadIdx.x;
    if (i < BN*NCH*NN) g_prob[i] = 1.0f / (1.0f + expf(-preds[i]));
}

// tiled transpose: highf [b][c][n] -> g_hft [b][n][c]
__global__ void k_transpose(const float* __restrict__ hf) {
    __shared__ float tile[32][33];
    int b = blockIdx.z;
    int n0 = blockIdx.x*32, c0 = blockIdx.y*32;
    const float* src = hf + (size_t)b*CHIGH*NN;
    tile[threadIdx.y][threadIdx.x] = src[(size_t)(c0+threadIdx.y)*NN + n0+threadIdx.x];
    __syncthreads();
    g_hft[((size_t)b*NN + n0+threadIdx.y)*CHIGH + c0+threadIdx.x] = tile[threadIdx.x][threadIdx.y];
}

// low tree: exact double (C=3)
__global__ void k_edgew_low(const float* __restrict__ feat) {
    int i = blockIdx.x*blockDim.x + threadIdx.x;
    if (i >= BN*EE) return;
    int b = i / EE, e = i % EE;
    int a, bb; edge_ep(e, a, bb);
    const float* f = feat + (size_t)b * CLOW * NN;
    double s = 0.0;
    #pragma unroll
    for (int c = 0; c < CLOW; c++) {
        double d = (double)f[c*NN + a] - (double)f[c*NN + bb];
        s += d * d;
    }
    g_wedge[0][i] = s;
}

// high tree: warp per edge, float4 over transposed feats, compensated fp32
// lane partials + exact double warp reduce. Error ~1e-9 << adjacent-weight gap.
__global__ __launch_bounds__(256) void k_edgew_high() {
    int w = (blockIdx.x*blockDim.x + threadIdx.x) >> 5;
    int lane = threadIdx.x & 31;
    if (w >= BN*EE) return;
    int b = w / EE, e = w % EE;
    int a, bb; edge_ep(e, a, bb);
    const float4* fa = (const float4*)(g_hft + ((size_t)b*NN + a)*CHIGH);
    const float4* fb = (const float4*)(g_hft + ((size_t)b*NN + bb)*CHIGH);
    float s = 0.f, comp = 0.f;
    #pragma unroll
    for (int k = 0; k < 4; k++) {
        float4 x = fa[lane + 32*k];
        float4 y = fb[lane + 32*k];
        float d0 = x.x - y.x, d1 = x.y - y.y, d2 = x.z - y.z, d3 = x.w - y.w;
        twosum(s, comp, d0*d0);
        twosum(s, comp, d1*d1);
        twosum(s, comp, d2*d2);
        twosum(s, comp, d3*d3);
    }
    double v = (double)s + (double)comp;
    #pragma unroll
    for (int off = 16; off; off >>= 1) v += __shfl_down_sync(0xffffffffu, v, off);
    if (lane == 0) g_wedge[1][w] = v;
}

// Boruvka MST, one block per (tree,batch), scratch in shared memory.
__global__ __launch_bounds__(1024) void k_boruvka_both() {
    int b = blockIdx.x & 3, tree = blockIdx.x >> 2;
    int tid = threadIdx.x, T = blockDim.x;
    const double* w = g_wedge[tree] + b*EE;
    int* mf = g_mst[tree] + b*EE;

    extern __shared__ char smraw[];
    unsigned long long* bw = (unsigned long long*)smraw;
    int* cp = (int*)(smraw + NN*8);
    int* be = cp + NN;
    int* lk = be + NN;

    for (int v = tid; v < NN; v += T) cp[v] = v;
    for (int e = tid; e < EE; e += T) mf[e] = 0;
    __syncthreads();

    __shared__ int s_any, s_chg;
    for (int round = 0; round < 14; round++) {
        for (int v = tid; v < NN; v += T) {
            bw[v] = 0xFFFFFFFFFFFFFFFFull;
            be[v] = 0x7FFFFFFF;
            lk[v] = v;
        }
        if (tid == 0) s_any = 0;
        __syncthreads();

        for (int e = tid; e < EE; e += T) {
            int a, bb; edge_ep(e, a, bb);
            int ca = cp[a], cb = cp[bb];
            if (ca != cb) {
                unsigned long long k = (unsigned long long)__double_as_longlong(w[e]);
                atomicMin(&bw[ca], k);
                atomicMin(&bw[cb], k);
                s_any = 1;
            }
        }
        __syncthreads();
        if (!s_any) break;

        for (int e = tid; e < EE; e += T) {
            int a, bb; edge_ep(e, a, bb);
            int ca = cp[a], cb = cp[bb];
            if (ca != cb) {
                unsigned long long k = (unsigned long long)__double_as_longlong(w[e]);
                if (k == bw[ca]) atomicMin(&be[ca], e);
                if (k == bw[cb]) atomicMin(&be[cb], e);
            }
        }
        __syncthreads();

        for (int v = tid; v < NN; v += T) {
            if (cp[v] == v && be[v] != 0x7FFFFFFF) {
                int e = be[v]; int a, bb; edge_ep(e, a, bb);
                int ca = cp[a], cb = cp[bb];
                lk[v] = (ca == v) ? cb : ca;
                mf[e] = 1;
            }
        }
        __syncthreads();

        for (int v = tid; v < NN; v += T) {
            int o = lk[v];
            if (o != v && lk[o] == v && v < o) lk[v] = v;
        }
        __syncthreads();

        for (int it = 0; it < 20; it++) {
            if (tid == 0) s_chg = 0;
            __syncthreads();
            for (int v = tid; v < NN; v += T) {
                int l = lk[v]; int ll = lk[l];
                if (l != ll) { lk[v] = ll; s_chg = 1; }
            }
            __syncthreads();
            if (!s_chg) break;
        }
        for (int v = tid; v < NN; v += T) cp[v] = lk[cp[v]];
        __syncthreads();
    }
}

// BFS with contiguous child ranges, traversal state in shared memory.
__global__ __launch_bounds__(256) void k_bfs_both() {
    int b = blockIdx.x & 3, tr = blockIdx.x >> 2;
    int tid = threadIdx.x, T = blockDim.x;
    extern __shared__ char sm[];
    unsigned char* flg = (unsigned char*)sm;      // NN
    int* ord = (int*)(sm + NN);                   // NN
    int* par = ord + NN;                          // NN (node -> parent node)
    const int* mf = g_mst[tr] + b*EE;

    for (int v = tid; v < NN; v += T) {
        int r = v / WW, c = v % WW;
        unsigned f = 0;
        if (c > 0      && mf[r*(WW-1) + c - 1])  f |= 1u;
        if (c < WW-1   && mf[r*(WW-1) + c])      f |= 2u;
        if (r > 0      && mf[EH + (r-1)*WW + c]) f |= 4u;
        if (r < HH-1   && mf[EH + r*WW + c])     f |= 8u;
        flg[v] = (unsigned char)f;
    }
    __shared__ int s_cnt;
    if (tid == 0) {
        ord[0] = 0; par[0] = -1;
        g_lvl[tr][b*(NN+2)] = 0; g_lvl[tr][b*(NN+2)+1] = 1;
        g_pp[tr][b*NN] = 0;
    }
    __syncthreads();

    int cur = 0, end = 1, d = 0;
    while (true) {
        if (tid == 0) s_cnt = 0;
        __syncthreads();
        for (int i = cur + tid; i < end; i += T) {
            int u = ord[i]; int pu = par[u];
            unsigned f = flg[u];
            int tmp[4]; int m = 0;
            if (f & 1u)  { int nb = u - 1;  if (nb != pu) tmp[m++] = nb; }
            if (f & 2u)  { int nb = u + 1;  if (nb != pu) tmp[m++] = nb; }
            if (f & 4u)  { int nb = u - WW; if (nb != pu) tmp[m++] = nb; }
            if (f & 8u)  { int nb = u + WW; if (nb != pu) tmp[m++] = nb; }
            int base = end + atomicAdd(&s_cnt, m);
            g_cs[tr][b*NN + i] = base;
            g_cn[tr][b*NN + i] = m;
            for (int j = 0; j < m; j++) {
                ord[base + j] = tmp[j];
                par[tmp[j]] = u;
                g_pp[tr][b*NN + base + j] = i;
            }
        }
        __syncthreads();
        int cnt = s_cnt;
        if (tid == 0) g_lvl[tr][b*(NN+2) + d + 2] = end + cnt;
        if (cnt == 0) { if (tid == 0) g_nlev[tr][b] = d + 1; break; }
        cur = end; end += cnt; d++;
        __syncthreads();
    }
    __syncthreads();
    for (int v = tid; v < NN; v += T) {
        g_ord[tr][b*NN + v] = ord[v];
        g_par[tr][b*NN + v] = par[v];
    }
}

// node weights (position-indexed). low: thread per position.
__global__ void k_nodew_low(const float* __restrict__ feat) {
    int i = blockIdx.x*blockDim.x + threadIdx.x;
    if (i >= BN*NN) return;
    int b = i / NN;
    int v = g_ord[0][i];
    int pu = g_par[0][b*NN + v];
    float wv = 0.0f;
    if (pu >= 0) {
        const float* f = feat + (size_t)b * CLOW * NN;
        float ss = 0.0f;
        #pragma unroll
        for (int c = 0; c < CLOW; c++) {
            float d = f[c*NN + v] - f[c*NN + pu];
            ss += d * d;
        }
        wv = expf(-ss / 0.02f);
    }
    g_wpos[0][i] = wv;
}

// high: warp per position with float4 loads from transposed feats.
__global__ __launch_bounds__(256) void k_nodew_high() {
    int w = (blockIdx.x*blockDim.x + threadIdx.x) >> 5;
    int lane = threadIdx.x & 31;
    if (w >= BN*NN) return;
    int b = w / NN;
    int v = g_ord[1][w];
    int pu = g_par[1][b*NN + v];
    float wv = 0.0f;
    if (pu >= 0) {
        const float4* fa = (const float4*)(g_hft + ((size_t)b*NN + v)*CHIGH);
        const float4* fb = (const float4*)(g_hft + ((size_t)b*NN + pu)*CHIGH);
        float ss = 0.0f;
        #pragma unroll
        for (int k = 0; k < 4; k++) {
            float4 x = fa[lane + 32*k];
            float4 y = fb[lane + 32*k];
            float d0 = x.x - y.x, d1 = x.y - y.y, d2 = x.z - y.z, d3 = x.w - y.w;
            ss += d0*d0 + d1*d1 + d2*d2 + d3*d3;
        }
        #pragma unroll
        for (int off = 16; off; off >>= 1) ss += __shfl_down_sync(0xffffffffu, ss, off);
        wv = expf(-ss);   // sigma = 1
    }
    if (lane == 0) g_wpos[1][w] = wv;
}

__global__ void k_invord1() {
    int i = blockIdx.x*blockDim.x + threadIdx.x;
    if (i < BN*NN) g_posN1[(i/NN)*NN + g_ord[1][i]] = i % NN;
}
__global__ void k_perm01() {
    int i = blockIdx.x*blockDim.x + threadIdx.x;
    if (i < BN*NN) g_perm01[i] = g_posN1[(i/NN)*NN + g_ord[0][i]];
}
// prob -> [b][c][pos0]
__global__ void k_permute0() {
    int i = blockIdx.x*blockDim.x + threadIdx.x;
    if (i >= BN*NN) return;
    int b = i / NN, p = i % NN;
    int u = g_ord[0][i];
    #pragma unroll
    for (int c = 0; c < NCH; c++)
        g_f0[((size_t)b*NCH + c)*NN + p] = g_prob[((size_t)b*NCH + c)*NN + u];
}

// tree DP, channel-group split, accumulator in shared memory (in-place down pass)
__global__ __launch_bounds__(DP_T) void k_treedp(int st) {
    int b = blockIdx.x / NGROUP, g = blockIdx.x % NGROUP;
    int tid = threadIdx.x;
    int tr = st;
    int nreal = (g == NGROUP-1) ? (NCH - 4*(NGROUP-1)) : 4;   // 4,4,4,4,4,1
    int cbase = g*4;
    extern __shared__ float smf[];
    float* A  = smf;          // 5*NN (channels local 0..nreal, norm at nreal)
    float* wv = smf + 5*NN;   // NN
    const int* cs  = g_cs[tr] + b*NN;
    const int* cn  = g_cn[tr] + b*NN;
    const int* pp  = g_pp[tr] + b*NN;
    const int* lvl = g_lvl[tr] + b*(NN+2);
    const float* FP = (st == 0 ? g_f0 : g_f1) + (size_t)b*NCH*NN;
    int D = g_nlev[tr][b];
    int CH = nreal + 1;

    for (int i = tid; i < NN; i += DP_T) wv[i] = g_wpos[tr][b*NN + i];
    __syncthreads();

    // up: children before parents
    for (int d = D - 1; d >= 0; d--) {
        int lo = lvl[d], cnt = lvl[d+1] - lo, m = cnt * CH;
        for (int t = tid; t < m; t += DP_T) {
            int c = t / cnt, idx = t - c*cnt, i = lo + idx;
            float acc = (c < nreal) ? FP[(size_t)(cbase + c)*NN + i] : 1.0f;
            int s0 = cs[i], n0 = cn[i];
            for (int j = s0; j < s0 + n0; j++) acc += wv[j] * A[c*NN + j];
            A[c*NN + i] = acc;
        }
        __syncthreads();
    }
    // down: parents before children (in place; root level is identity)
    for (int d = 1; d < D; d++) {
        int lo = lvl[d], cnt = lvl[d+1] - lo, m = cnt * CH;
        for (int t = tid; t < m; t += DP_T) {
            int c = t / cnt, idx = t - c*cnt, i = lo + idx;
            float av = A[c*NN + i];
            float wu = wv[i];
            A[c*NN + i] = av + wu * (A[c*NN + pp[i]] - wu * av);
        }
        __syncthreads();
    }
    // normalize + write
    for (int t = tid; t < NN*nreal; t += DP_T) {
        int c = t / NN, i = t - c*NN;
        float val = A[c*NN + i] / A[nreal*NN + i];
        if (st == 0) {
            g_f1[((size_t)b*NCH + cbase + c)*NN + g_perm01[b*NN + i]] = val;
        } else {
            g_AS2[(size_t)b*NCH*NN + (size_t)(cbase + c)*NN + g_ord[1][b*NN + i]] = val;
        }
    }
}

__global__ void k_zero_acc() { g_acc[0] = 0.0; g_acc[1] = 0.0; }

__global__ __launch_bounds__(256) void k_loss(const float* __restrict__ roi) {
    double lsum = 0.0, nsum = 0.0;
    int stride = gridDim.x * blockDim.x;
    for (int idx = blockIdx.x*blockDim.x + threadIdx.x; idx < BN*NCH*NN; idx += stride) {
        int v = idx % NN;
        int bc = idx / NN;
        int c = bc % NCH, b = bc / NCH;
        int h = v / WW, wd = v % WW;
        float r = roi[b*(2*HH)*(2*WW) + (2*h)*(2*WW) + 2*wd];
        lsum += (double)(r * fabsf(g_prob[idx] - g_AS2[idx]));
        if (c == 0) nsum += (double)r;
    }
    __shared__ double shl[256], shn[256];
    int tid = threadIdx.x;
    shl[tid] = lsum; shn[tid] = nsum;
    __syncthreads();
    for (int off = 128; off > 0; off >>= 1) {
        if (tid < off) { shl[tid] += shl[tid+off]; shn[tid] += shn[tid+off]; }
        __syncthreads();
    }
    if (tid == 0) {
        atomicAdd(&g_acc[0], shl[0]);
        atomicAdd(&g_acc[1], shn[0]);
    }
}

__global__ void k_write(float* out) {
    double n = g_acc[1];
    out[0] = (n > 0.0) ? (float)(g_acc[0] / n) : 0.0f;
}

// ---------------- launch ----------------
extern "C" void kernel_launch(void* const* d_in, const int* in_sizes, int n_in,
                              void* d_out, int out_size) {
    const float *preds = nullptr, *lowf = nullptr, *highf = nullptr, *roi = nullptr;
    for (int i = 0; i < n_in; i++) {
        switch (in_sizes[i]) {
            case BN*NCH*NN:        preds = (const float*)d_in[i]; break;
            case BN*CLOW*NN:       lowf  = (const float*)d_in[i]; break;
            case BN*CHIGH*NN:      highf = (const float*)d_in[i]; break;
            case BN*(2*HH)*(2*WW): roi   = (const float*)d_in[i]; break;
        }
    }
    float* out = (float*)d_out;

    static int attr_done = 0;
    if (!attr_done) {
        cudaFuncSetAttribute(k_boruvka_both, cudaFuncAttributeMaxDynamicSharedMemorySize, SMEM_BORUVKA);
        cudaFuncSetAttribute(k_bfs_both,     cudaFuncAttributeMaxDynamicSharedMemorySize, BFS_SMEM);
        cudaFuncSetAttribute(k_treedp,       cudaFuncAttributeMaxDynamicSharedMemorySize, DP_SMEM);
        attr_done = 1;
    }

    k_sigmoid<<<(BN*NCH*NN + 255)/256, 256>>>(preds);
    k_transpose<<<dim3(NN/32, CHIGH/32, BN), dim3(32,32)>>>(highf);

    k_edgew_low <<<(BN*EE + 127)/128, 128>>>(lowf);
    k_edgew_high<<<(BN*EE*32 + 255)/256, 256>>>();

    k_boruvka_both<<<2*BN, 1024, SMEM_BORUVKA>>>();
    k_bfs_both<<<2*BN, 256, BFS_SMEM>>>();

    k_nodew_low <<<(BN*NN + 127)/128, 128>>>(lowf);
    k_nodew_high<<<(BN*NN*32 + 255)/256, 256>>>();

    k_invord1 <<<(BN*NN + 255)/256, 256>>>();
    k_perm01  <<<(BN*NN + 255)/256, 256>>>();
    k_permute0<<<(BN*NN + 255)/256, 256>>>();

    k_treedp<<<BN*NGROUP, DP_T, DP_SMEM>>>(0);
    k_treedp<<<BN*NGROUP, DP_T, DP_SMEM>>>(1);

    k_zero_acc<<<1, 1>>>();
    k_loss<<<1024, 256>>>(roi);
    k_write<<<1, 1>>>(out);
    (void)out_size;
}

// round 5
// speedup vs baseline: 2.6824x; 1.5433x over previous
#include <cuda_runtime.h>
#include <math.h>

#define BN 4
#define HH 96
#define WW 96
#define NN (HH*WW)        // 9216
#define EH (HH*(WW-1))    // 9120
#define EV ((HH-1)*WW)    // 9120
#define EE (EH+EV)        // 18240
#define NCH 21
#define CLOW 3
#define CHIGH 512
#define NGROUP 11         // channel groups for DP: 10 groups of 2 + 1 group of 1
#define DP_T 256
#define LVCAP 4096
#define DP_SMEM (3*NN*4 + NN*4 + NN*4 + LVCAP*4)   // A + wv + topo + lvl = 200704 B
#define BFS_SMEM (NN + 3*NN*4)                      // flags + ord + par + topo = 119808 B
#define SMEM_BORUVKA (NN*(8+4+4+4))                 // 184320 B

// ---------------- device scratch ----------------
__device__ float  g_prob[BN*NCH*NN];
__device__ float  g_AS2 [BN*NCH*NN];
__device__ float  g_hft [(size_t)BN*NN*CHIGH];  // high feats transposed [b][n][c]
__device__ double g_wedge[2][BN*EE];
__device__ int    g_mst [2][BN*EE];
__device__ int    g_ord [2][BN*NN];       // position -> node
__device__ int    g_par [2][BN*NN];       // node -> parent node (-1 root)
__device__ unsigned g_topo[2][BN*NN];     // position -> pp | cs<<14 | cn<<28
__device__ float  g_wpos[2][BN*NN];       // position -> parent-edge weight (root 0)
__device__ int    g_lvl [2][BN*(NN+2)];
__device__ int    g_nlev[2][BN];
__device__ int    g_posN1[BN*NN];         // tree1: node -> position
__device__ int    g_perm01[BN*NN];        // tree0 pos -> tree1 pos
__device__ float  g_f0[BN*NCH*NN];        // stage0 features [b][c][pos0]
__device__ float  g_f1[BN*NCH*NN];        // stage1 features [b][c][pos1]
__device__ double g_acc[2];

__device__ __forceinline__ void edge_ep(int e, int& a, int& b) {
    if (e < EH) { int r = e / (WW-1), c = e % (WW-1); a = r*WW + c; b = a + 1; }
    else        { int j = e - EH;                      a = j;        b = j + WW; }
}
__device__ __forceinline__ void twosum(float& s, float& comp, float p) {
    float t = s + p;
    float z = t - s;
    float e = (s - (t - z)) + (p - z);
    s = t; comp += e;
}

// ---------------- kernels ----------------

__global__ void k_sigmoid(const float* __restrict__ preds) {
    int i = blockIdx.x*blockDim.x + threadIdx.x;
    if (i < BN*NCH*NN) g_prob[i] = 1.0f / (1.0f + expf(-preds[i]));
}

// tiled transpose: highf [b][c][n] -> g_hft [b][n][c]
__global__ void k_transpose(const float* __restrict__ hf) {
    __shared__ float tile[32][33];
    int b = blockIdx.z;
    int n0 = blockIdx.x*32, c0 = blockIdx.y*32;
    const float* src = hf + (size_t)b*CHIGH*NN;
    tile[threadIdx.y][threadIdx.x] = src[(size_t)(c0+threadIdx.y)*NN + n0+threadIdx.x];
    __syncthreads();
    g_hft[((size_t)b*NN + n0+threadIdx.y)*CHIGH + c0+threadIdx.x] = tile[threadIdx.x][threadIdx.y];
}

// low tree: exact double (C=3)
__global__ void k_edgew_low(const float* __restrict__ feat) {
    int i = blockIdx.x*blockDim.x + threadIdx.x;
    if (i >= BN*EE) return;
    int b = i / EE, e = i % EE;
    int a, bb; edge_ep(e, a, bb);
    const float* f = feat + (size_t)b * CLOW * NN;
    double s = 0.0;
    #pragma unroll
    for (int c = 0; c < CLOW; c++) {
        double d = (double)f[c*NN + a] - (double)f[c*NN + bb];
        s += d * d;
    }
    g_wedge[0][i] = s;
}

// high tree: warp per edge, float4 loads, compensated fp32 + double warp reduce.
__global__ __launch_bounds__(256) void k_edgew_high() {
    int w = (blockIdx.x*blockDim.x + threadIdx.x) >> 5;
    int lane = threadIdx.x & 31;
    if (w >= BN*EE) return;
    int b = w / EE, e = w % EE;
    int a, bb; edge_ep(e, a, bb);
    const float4* fa = (const float4*)(g_hft + ((size_t)b*NN + a)*CHIGH);
    const float4* fb = (const float4*)(g_hft + ((size_t)b*NN + bb)*CHIGH);
    float s = 0.f, comp = 0.f;
    #pragma unroll
    for (int k = 0; k < 4; k++) {
        float4 x = fa[lane + 32*k];
        float4 y = fb[lane + 32*k];
        float d0 = x.x - y.x, d1 = x.y - y.y, d2 = x.z - y.z, d3 = x.w - y.w;
        twosum(s, comp, d0*d0);
        twosum(s, comp, d1*d1);
        twosum(s, comp, d2*d2);
        twosum(s, comp, d3*d3);
    }
    double v = (double)s + (double)comp;
    #pragma unroll
    for (int off = 16; off; off >>= 1) v += __shfl_down_sync(0xffffffffu, v, off);
    if (lane == 0) g_wedge[1][w] = v;
}

// Boruvka MST, one block per (tree,batch), scratch in shared memory.
__global__ __launch_bounds__(1024) void k_boruvka_both() {
    int b = blockIdx.x & 3, tree = blockIdx.x >> 2;
    int tid = threadIdx.x, T = blockDim.x;
    const double* w = g_wedge[tree] + b*EE;
    int* mf = g_mst[tree] + b*EE;

    extern __shared__ char smraw[];
    unsigned long long* bw = (unsigned long long*)smraw;
    int* cp = (int*)(smraw + NN*8);
    int* be = cp + NN;
    int* lk = be + NN;

    for (int v = tid; v < NN; v += T) cp[v] = v;
    for (int e = tid; e < EE; e += T) mf[e] = 0;
    __syncthreads();

    __shared__ int s_any, s_chg;
    for (int round = 0; round < 14; round++) {
        for (int v = tid; v < NN; v += T) {
            bw[v] = 0xFFFFFFFFFFFFFFFFull;
            be[v] = 0x7FFFFFFF;
            lk[v] = v;
        }
        if (tid == 0) s_any = 0;
        __syncthreads();

        for (int e = tid; e < EE; e += T) {
            int a, bb; edge_ep(e, a, bb);
            int ca = cp[a], cb = cp[bb];
            if (ca != cb) {
                unsigned long long k = (unsigned long long)__double_as_longlong(w[e]);
                atomicMin(&bw[ca], k);
                atomicMin(&bw[cb], k);
                s_any = 1;
            }
        }
        __syncthreads();
        if (!s_any) break;

        for (int e = tid; e < EE; e += T) {
            int a, bb; edge_ep(e, a, bb);
            int ca = cp[a], cb = cp[bb];
            if (ca != cb) {
                unsigned long long k = (unsigned long long)__double_as_longlong(w[e]);
                if (k == bw[ca]) atomicMin(&be[ca], e);
                if (k == bw[cb]) atomicMin(&be[cb], e);
            }
        }
        __syncthreads();

        for (int v = tid; v < NN; v += T) {
            if (cp[v] == v && be[v] != 0x7FFFFFFF) {
                int e = be[v]; int a, bb; edge_ep(e, a, bb);
                int ca = cp[a], cb = cp[bb];
                lk[v] = (ca == v) ? cb : ca;
                mf[e] = 1;
            }
        }
        __syncthreads();

        for (int v = tid; v < NN; v += T) {
            int o = lk[v];
            if (o != v && lk[o] == v && v < o) lk[v] = v;
        }
        __syncthreads();

        for (int it = 0; it < 20; it++) {
            if (tid == 0) s_chg = 0;
            __syncthreads();
            for (int v = tid; v < NN; v += T) {
                int l = lk[v]; int ll = lk[l];
                if (l != ll) { lk[v] = ll; s_chg = 1; }
            }
            __syncthreads();
            if (!s_chg) break;
        }
        for (int v = tid; v < NN; v += T) cp[v] = lk[cp[v]];
        __syncthreads();
    }
}

// BFS with contiguous child ranges + packed topology, all state in shared mem.
__global__ __launch_bounds__(256) void k_bfs_both() {
    int b = blockIdx.x & 3, tr = blockIdx.x >> 2;
    int tid = threadIdx.x, T = blockDim.x;
    extern __shared__ char sm[];
    unsigned char* flg = (unsigned char*)sm;        // NN
    int* ord = (int*)(sm + NN);                     // NN
    int* par = ord + NN;                            // NN (node -> parent node)
    unsigned* topo = (unsigned*)(par + NN);         // NN (pp | cs<<14 | cn<<28)
    const int* mf = g_mst[tr] + b*EE;

    for (int v = tid; v < NN; v += T) {
        int r = v / WW, c = v % WW;
        unsigned f = 0;
        if (c > 0      && mf[r*(WW-1) + c - 1])  f |= 1u;
        if (c < WW-1   && mf[r*(WW-1) + c])      f |= 2u;
        if (r > 0      && mf[EH + (r-1)*WW + c]) f |= 4u;
        if (r < HH-1   && mf[EH + r*WW + c])     f |= 8u;
        flg[v] = (unsigned char)f;
        topo[v] = 0u;
    }
    __shared__ int s_cnt;
    if (tid == 0) {
        ord[0] = 0; par[0] = -1;
        g_lvl[tr][b*(NN+2)] = 0; g_lvl[tr][b*(NN+2)+1] = 1;
    }
    __syncthreads();

    int cur = 0, end = 1, d = 0;
    while (true) {
        if (tid == 0) s_cnt = 0;
        __syncthreads();
        for (int i = cur + tid; i < end; i += T) {
            int u = ord[i]; int pu = par[u];
            unsigned f = flg[u];
            int tmp[4]; int m = 0;
            if (f & 1u)  { int nb = u - 1;  if (nb != pu) tmp[m++] = nb; }
            if (f & 2u)  { int nb = u + 1;  if (nb != pu) tmp[m++] = nb; }
            if (f & 4u)  { int nb = u - WW; if (nb != pu) tmp[m++] = nb; }
            if (f & 8u)  { int nb = u + WW; if (nb != pu) tmp[m++] = nb; }
            int base = end + atomicAdd(&s_cnt, m);
            topo[i] |= ((unsigned)base << 14) | ((unsigned)m << 28);
            for (int j = 0; j < m; j++) {
                ord[base + j] = tmp[j];
                par[tmp[j]] = u;
                topo[base + j] = (unsigned)i;   // pp field; cs/cn filled next level
            }
        }
        __syncthreads();
        int cnt = s_cnt;
        if (tid == 0) g_lvl[tr][b*(NN+2) + d + 2] = end + cnt;
        if (cnt == 0) { if (tid == 0) g_nlev[tr][b] = d + 1; break; }
        cur = end; end += cnt; d++;
        __syncthreads();
    }
    __syncthreads();
    for (int v = tid; v < NN; v += T) {
        g_ord[tr][b*NN + v] = ord[v];
        g_par[tr][b*NN + v] = par[v];
        g_topo[tr][b*NN + v] = topo[v];
    }
}

// node weights (position-indexed). low: thread per position.
__global__ void k_nodew_low(const float* __restrict__ feat) {
    int i = blockIdx.x*blockDim.x + threadIdx.x;
    if (i >= BN*NN) return;
    int b = i / NN;
    int v = g_ord[0][i];
    int pu = g_par[0][b*NN + v];
    float wv = 0.0f;
    if (pu >= 0) {
        const float* f = feat + (size_t)b * CLOW * NN;
        float ss = 0.0f;
        #pragma unroll
        for (int c = 0; c < CLOW; c++) {
            float d = f[c*NN + v] - f[c*NN + pu];
            ss += d * d;
        }
        wv = expf(-ss / 0.02f);
    }
    g_wpos[0][i] = wv;
}

// high: warp per position, float4 loads from transposed feats.
__global__ __launch_bounds__(256) void k_nodew_high() {
    int w = (blockIdx.x*blockDim.x + threadIdx.x) >> 5;
    int lane = threadIdx.x & 31;
    if (w >= BN*NN) return;
    int b = w / NN;
    int v = g_ord[1][w];
    int pu = g_par[1][b*NN + v];
    float wv = 0.0f;
    if (pu >= 0) {
        const float4* fa = (const float4*)(g_hft + ((size_t)b*NN + v)*CHIGH);
        const float4* fb = (const float4*)(g_hft + ((size_t)b*NN + pu)*CHIGH);
        float ss = 0.0f;
        #pragma unroll
        for (int k = 0; k < 4; k++) {
            float4 x = fa[lane + 32*k];
            float4 y = fb[lane + 32*k];
            float d0 = x.x - y.x, d1 = x.y - y.y, d2 = x.z - y.z, d3 = x.w - y.w;
            ss += d0*d0 + d1*d1 + d2*d2 + d3*d3;
        }
        #pragma unroll
        for (int off = 16; off; off >>= 1) ss += __shfl_down_sync(0xffffffffu, ss, off);
        wv = expf(-ss);   // sigma = 1
    }
    if (lane == 0) g_wpos[1][w] = wv;
}

__global__ void k_invord1() {
    int i = blockIdx.x*blockDim.x + threadIdx.x;
    if (i < BN*NN) g_posN1[(i/NN)*NN + g_ord[1][i]] = i % NN;
}
__global__ void k_perm01() {
    int i = blockIdx.x*blockDim.x + threadIdx.x;
    if (i < BN*NN) g_perm01[i] = g_posN1[(i/NN)*NN + g_ord[0][i]];
}
// prob -> [b][c][pos0]
__global__ void k_permute0() {
    int i = blockIdx.x*blockDim.x + threadIdx.x;
    if (i >= BN*NN) return;
    int b = i / NN, p = i % NN;
    int u = g_ord[0][i];
    #pragma unroll
    for (int c = 0; c < NCH; c++)
        g_f0[((size_t)b*NCH + c)*NN + p] = g_prob[((size_t)b*NCH + c)*NN + u];
}

// tree DP: everything (A, weights, topology, level offsets) in shared memory.
__global__ __launch_bounds__(DP_T) void k_treedp(int st) {
    int b = blockIdx.x / NGROUP, g = blockIdx.x % NGROUP;
    int tid = threadIdx.x;
    int tr = st;
    int nreal = (g == NGROUP-1) ? (NCH - 2*(NGROUP-1)) : 2;   // 2×10 + 1
    int cbase = g*2;
    int CH = nreal + 1;

    extern __shared__ char smraw2[];
    float* A      = (float*)smraw2;                  // 3*NN
    float* wv     = (float*)(smraw2 + 3*NN*4);       // NN
    unsigned* tp  = (unsigned*)(smraw2 + 4*NN*4);    // NN
    int* slvl     = (int*)(smraw2 + 5*NN*4);         // LVCAP

    const float* FP = (st == 0 ? g_f0 : g_f1) + (size_t)b*NCH*NN;
    int D = g_nlev[tr][b];
    int nlv = D + 1;
    if (nlv > LVCAP) nlv = LVCAP;

    for (int i = tid; i < NN; i += DP_T) {
        wv[i] = g_wpos[tr][b*NN + i];
        tp[i] = g_topo[tr][b*NN + i];
    }
    for (int i = tid; i < nlv; i += DP_T) slvl[i] = g_lvl[tr][b*(NN+2) + i];
    // init A from features (norm channel = 1)
    for (int c = 0; c < nreal; c++)
        for (int i = tid; i < NN; i += DP_T) A[c*NN + i] = FP[(size_t)(cbase + c)*NN + i];
    for (int i = tid; i < NN; i += DP_T) A[nreal*NN + i] = 1.0f;
    __syncthreads();

    // up: children before parents (in place: A starts at f)
    for (int d = D - 1; d >= 0; d--) {
        int lo = (d < LVCAP) ? slvl[d] : g_lvl[tr][b*(NN+2) + d];
        int hi = (d+1 < LVCAP) ? slvl[d+1] : g_lvl[tr][b*(NN+2) + d + 1];
        int cnt = hi - lo, m = cnt * CH;
        for (int t = tid; t < m; t += DP_T) {
            int c = t / cnt, i = lo + (t - c*cnt);
            unsigned u = tp[i];
            int cs = (u >> 14) & 0x3FFF, cn = u >> 28;
            float acc = A[c*NN + i];
            for (int j = cs; j < cs + cn; j++) acc += wv[j] * A[c*NN + j];
            A[c*NN + i] = acc;
        }
        __syncthreads();
    }
    // down: parents before children (in place; root level identity)
    for (int d = 1; d < D; d++) {
        int lo = (d < LVCAP) ? slvl[d] : g_lvl[tr][b*(NN+2) + d];
        int hi = (d+1 < LVCAP) ? slvl[d+1] : g_lvl[tr][b*(NN+2) + d + 1];
        int cnt = hi - lo, m = cnt * CH;
        for (int t = tid; t < m; t += DP_T) {
            int c = t / cnt, i = lo + (t - c*cnt);
            int pp = tp[i] & 0x3FFF;
            float av = A[c*NN + i];
            float wu = wv[i];
            A[c*NN + i] = av + wu * (A[c*NN + pp] - wu * av);
        }
        __syncthreads();
    }
    // normalize + write
    for (int t = tid; t < NN*nreal; t += DP_T) {
        int c = t / NN, i = t - c*NN;
        float val = A[c*NN + i] / A[nreal*NN + i];
        if (st == 0) {
            g_f1[((size_t)b*NCH + cbase + c)*NN + g_perm01[b*NN + i]] = val;
        } else {
            g_AS2[(size_t)b*NCH*NN + (size_t)(cbase + c)*NN + g_ord[1][b*NN + i]] = val;
        }
    }
}

__global__ void k_zero_acc() { g_acc[0] = 0.0; g_acc[1] = 0.0; }

__global__ __launch_bounds__(256) void k_loss(const float* __restrict__ roi) {
    double lsum = 0.0, nsum = 0.0;
    int stride = gridDim.x * blockDim.x;
    for (int idx = blockIdx.x*blockDim.x + threadIdx.x; idx < BN*NCH*NN; idx += stride) {
        int v = idx % NN;
        int bc = idx / NN;
        int c = bc % NCH, b = bc / NCH;
        int h = v / WW, wd = v % WW;
        float r = roi[b*(2*HH)*(2*WW) + (2*h)*(2*WW) + 2*wd];
        lsum += (double)(r * fabsf(g_prob[idx] - g_AS2[idx]));
        if (c == 0) nsum += (double)r;
    }
    __shared__ double shl[256], shn[256];
    int tid = threadIdx.x;
    shl[tid] = lsum; shn[tid] = nsum;
    __syncthreads();
    for (int off = 128; off > 0; off >>= 1) {
        if (tid < off) { shl[tid] += shl[tid+off]; shn[tid] += shn[tid+off]; }
        __syncthreads();
    }
    if (tid == 0) {
        atomicAdd(&g_acc[0], shl[0]);
        atomicAdd(&g_acc[1], shn[0]);
    }
}

__global__ void k_write(float* out) {
    double n = g_acc[1];
    out[0] = (n > 0.0) ? (float)(g_acc[0] / n) : 0.0f;
}

// ---------------- launch ----------------
extern "C" void kernel_launch(void* const* d_in, const int* in_sizes, int n_in,
                              void* d_out, int out_size) {
    const float *preds = nullptr, *lowf = nullptr, *highf = nullptr, *roi = nullptr;
    for (int i = 0; i < n_in; i++) {
        switch (in_sizes[i]) {
            case BN*NCH*NN:        preds = (const float*)d_in[i]; break;
            case BN*CLOW*NN:       lowf  = (const float*)d_in[i]; break;
            case BN*CHIGH*NN:      highf = (const float*)d_in[i]; break;
            case BN*(2*HH)*(2*WW): roi   = (const float*)d_in[i]; break;
        }
    }
    float* out = (float*)d_out;

    static int attr_done = 0;
    if (!attr_done) {
        cudaFuncSetAttribute(k_boruvka_both, cudaFuncAttributeMaxDynamicSharedMemorySize, SMEM_BORUVKA);
        cudaFuncSetAttribute(k_bfs_both,     cudaFuncAttributeMaxDynamicSharedMemorySize, BFS_SMEM);
        cudaFuncSetAttribute(k_treedp,       cudaFuncAttributeMaxDynamicSharedMemorySize, DP_SMEM);
        attr_done = 1;
    }

    k_sigmoid<<<(BN*NCH*NN + 255)/256, 256>>>(preds);
    k_transpose<<<dim3(NN/32, CHIGH/32, BN), dim3(32,32)>>>(highf);

    k_edgew_low <<<(BN*EE + 127)/128, 128>>>(lowf);
    k_edgew_high<<<(BN*EE*32 + 255)/256, 256>>>();

    k_boruvka_both<<<2*BN, 1024, SMEM_BORUVKA>>>();
    k_bfs_both<<<2*BN, 256, BFS_SMEM>>>();

    k_nodew_low <<<(BN*NN + 127)/128, 128>>>(lowf);
    k_nodew_high<<<(BN*NN*32 + 255)/256, 256>>>();

    k_invord1 <<<(BN*NN + 255)/256, 256>>>();
    k_perm01  <<<(BN*NN + 255)/256, 256>>>();
    k_permute0<<<(BN*NN + 255)/256, 256>>>();

    k_treedp<<<BN*NGROUP, DP_T, DP_SMEM>>>(0);
    k_treedp<<<BN*NGROUP, DP_T, DP_SMEM>>>(1);

    k_zero_acc<<<1, 1>>>();
    k_loss<<<1024, 256>>>(roi);
    k_write<<<1, 1>>>(out);
    (void)out_size;
}

// round 6
// speedup vs baseline: 2.7427x; 1.0225x over previous
#include <cuda_runtime.h>
#include <math.h>

#define BN 4
#define HH 96
#define WW 96
#define NN (HH*WW)        // 9216
#define EH (HH*(WW-1))    // 9120
#define EV ((HH-1)*WW)    // 9120
#define EE (EH+EV)        // 18240  (< 2^15)
#define NCH 21
#define CLOW 3
#define CHIGH 512
#define NGROUP 11         // channel groups for DP: 10 groups of 2 + 1 group of 1
#define DP_T 256
#define LVCAP (NN+2)
#define DP_SMEM (3*NN*4 + NN*4 + NN*4 + LVCAP*4)   // A + wv + topo + lvl = 221192 B
#define BFS_SMEM (NN + 3*NN*4)                      // flags + ord + par + topo = 119808 B
#define SMEM_BORUVKA (NN*16)                        // bw(8) + cp(4) + lk(4) = 147456 B

// ---------------- device scratch ----------------
__device__ float  g_prob[BN*NCH*NN];
__device__ float  g_AS2 [BN*NCH*NN];
__device__ float  g_hft [(size_t)BN*NN*CHIGH];      // high feats transposed [b][n][c]
__device__ unsigned long long g_wkey[2][BN*EE];     // fused (weight_bits & ~0x7FFF) | edge
__device__ int    g_mst [2][BN*EE];
__device__ int    g_ord [2][BN*NN];       // position -> node
__device__ int    g_par [2][BN*NN];       // node -> parent node (-1 root)
__device__ unsigned g_topo[2][BN*NN];     // position -> pp | cs<<14 | cn<<28
__device__ float  g_wpos[2][BN*NN];       // position -> parent-edge weight (root 0)
__device__ int    g_lvl [2][BN*(NN+2)];
__device__ int    g_nlev[2][BN];
__device__ int    g_posN1[BN*NN];         // tree1: node -> position
__device__ int    g_perm01[BN*NN];        // tree0 pos -> tree1 pos
__device__ float  g_f0[BN*NCH*NN];        // stage0 features [b][c][pos0]
__device__ float  g_f1[BN*NCH*NN];        // stage1 features [b][c][pos1]
__device__ double g_acc[2];

__device__ __forceinline__ void edge_ep(int e, int& a, int& b) {
    if (e < EH) { int r = e / (WW-1), c = e % (WW-1); a = r*WW + c; b = a + 1; }
    else        { int j = e - EH;                      a = j;        b = j + WW; }
}
__device__ __forceinline__ void twosum(float& s, float& comp, float p) {
    float t = s + p;
    float z = t - s;
    float e = (s - (t - z)) + (p - z);
    s = t; comp += e;
}
// fused key: weight bit-pattern (positive double => order-preserving) with the
// low 15 bits replaced by the edge index. Perturbation 2^-37 relative; distinct
// continuous weights differ by ~1e-5 relative => ordering/MST unchanged, and
// ties (prob 0) break by edge index exactly like the reference's stable sort.
__device__ __forceinline__ unsigned long long fuse_key(double w, int e) {
    return ((unsigned long long)__double_as_longlong(w) & 0xFFFFFFFFFFFF8000ull)
           | (unsigned long long)e;
}

// ---------------- kernels ----------------

__global__ void k_sigmoid(const float* __restrict__ preds) {
    int i = blockIdx.x*blockDim.x + threadIdx.x;
    if (i < BN*NCH*NN) g_prob[i] = 1.0f / (1.0f + expf(-preds[i]));
}

// tiled transpose: highf [b][c][n] -> g_hft [b][n][c]
__global__ void k_transpose(const float* __restrict__ hf) {
    __shared__ float tile[32][33];
    int b = blockIdx.z;
    int n0 = blockIdx.x*32, c0 = blockIdx.y*32;
    const float* src = hf + (size_t)b*CHIGH*NN;
    tile[threadIdx.y][threadIdx.x] = src[(size_t)(c0+threadIdx.y)*NN + n0+threadIdx.x];
    __syncthreads();
    g_hft[((size_t)b*NN + n0+threadIdx.y)*CHIGH + c0+threadIdx.x] = tile[threadIdx.x][threadIdx.y];
}

// low tree: exact double (C=3), fused key out
__global__ void k_edgew_low(const float* __restrict__ feat) {
    int i = blockIdx.x*blockDim.x + threadIdx.x;
    if (i >= BN*EE) return;
    int b = i / EE, e = i % EE;
    int a, bb; edge_ep(e, a, bb);
    const float* f = feat + (size_t)b * CLOW * NN;
    double s = 0.0;
    #pragma unroll
    for (int c = 0; c < CLOW; c++) {
        double d = (double)f[c*NN + a] - (double)f[c*NN + bb];
        s += d * d;
    }
    g_wkey[0][i] = fuse_key(s, e);
}

// high tree: warp per edge, float4 loads, compensated fp32 + double warp reduce.
__global__ __launch_bounds__(256) void k_edgew_high() {
    int w = (blockIdx.x*blockDim.x + threadIdx.x) >> 5;
    int lane = threadIdx.x & 31;
    if (w >= BN*EE) return;
    int b = w / EE, e = w % EE;
    int a, bb; edge_ep(e, a, bb);
    const float4* fa = (const float4*)(g_hft + ((size_t)b*NN + a)*CHIGH);
    const float4* fb = (const float4*)(g_hft + ((size_t)b*NN + bb)*CHIGH);
    float s = 0.f, comp = 0.f;
    #pragma unroll
    for (int k = 0; k < 4; k++) {
        float4 x = fa[lane + 32*k];
        float4 y = fb[lane + 32*k];
        float d0 = x.x - y.x, d1 = x.y - y.y, d2 = x.z - y.z, d3 = x.w - y.w;
        twosum(s, comp, d0*d0);
        twosum(s, comp, d1*d1);
        twosum(s, comp, d2*d2);
        twosum(s, comp, d3*d3);
    }
    double v = (double)s + (double)comp;
    #pragma unroll
    for (int off = 16; off; off >>= 1) v += __shfl_down_sync(0xffffffffu, v, off);
    if (lane == 0) g_wkey[1][w] = fuse_key(v, e);
}

// Boruvka MST, single-phase (fused keys), one block per (tree,batch), smem scratch.
__global__ __launch_bounds__(1024) void k_boruvka_both() {
    int b = blockIdx.x & 3, tree = blockIdx.x >> 2;
    int tid = threadIdx.x, T = blockDim.x;
    const unsigned long long* wk = g_wkey[tree] + b*EE;
    int* mf = g_mst[tree] + b*EE;

    extern __shared__ char smraw[];
    unsigned long long* bw = (unsigned long long*)smraw;   // NN*8
    int* cp = (int*)(smraw + NN*8);                         // NN*4
    int* lk = cp + NN;                                      // NN*4

    for (int v = tid; v < NN; v += T) cp[v] = v;
    for (int e = tid; e < EE; e += T) mf[e] = 0;
    __syncthreads();

    __shared__ int s_any, s_chg;
    for (int round = 0; round < 14; round++) {
        for (int v = tid; v < NN; v += T) {
            bw[v] = 0xFFFFFFFFFFFFFFFFull;
            lk[v] = v;
        }
        if (tid == 0) s_any = 0;
        __syncthreads();

        // per-component min (weight,edge) in one scan
        for (int e = tid; e < EE; e += T) {
            int a, bb; edge_ep(e, a, bb);
            int ca = cp[a], cb = cp[bb];
            if (ca != cb) {
                unsigned long long k = wk[e];
                atomicMin(&bw[ca], k);
                atomicMin(&bw[cb], k);
                s_any = 1;
            }
        }
        __syncthreads();
        if (!s_any) break;

        // hooking
        for (int v = tid; v < NN; v += T) {
            if (cp[v] == v && bw[v] != 0xFFFFFFFFFFFFFFFFull) {
                int e = (int)(bw[v] & 0x7FFFull);
                int a, bb; edge_ep(e, a, bb);
                int ca = cp[a], cb = cp[bb];
                lk[v] = (ca == v) ? cb : ca;
                mf[e] = 1;
            }
        }
        __syncthreads();

        // break mutual 2-cycles
        for (int v = tid; v < NN; v += T) {
            int o = lk[v];
            if (o != v && lk[o] == v && v < o) lk[v] = v;
        }
        __syncthreads();

        // pointer jumping
        for (int it = 0; it < 20; it++) {
            if (tid == 0) s_chg = 0;
            __syncthreads();
            for (int v = tid; v < NN; v += T) {
                int l = lk[v]; int ll = lk[l];
                if (l != ll) { lk[v] = ll; s_chg = 1; }
            }
            __syncthreads();
            if (!s_chg) break;
        }
        for (int v = tid; v < NN; v += T) cp[v] = lk[cp[v]];
        __syncthreads();
    }
}

// BFS with contiguous child ranges + packed topology, all state in shared mem.
__global__ __launch_bounds__(256) void k_bfs_both() {
    int b = blockIdx.x & 3, tr = blockIdx.x >> 2;
    int tid = threadIdx.x, T = blockDim.x;
    extern __shared__ char sm[];
    unsigned char* flg = (unsigned char*)sm;        // NN
    int* ord = (int*)(sm + NN);                     // NN
    int* par = ord + NN;                            // NN (node -> parent node)
    unsigned* topo = (unsigned*)(par + NN);         // NN (pp | cs<<14 | cn<<28)
    const int* mf = g_mst[tr] + b*EE;

    for (int v = tid; v < NN; v += T) {
        int r = v / WW, c = v % WW;
        unsigned f = 0;
        if (c > 0      && mf[r*(WW-1) + c - 1])  f |= 1u;
        if (c < WW-1   && mf[r*(WW-1) + c])      f |= 2u;
        if (r > 0      && mf[EH + (r-1)*WW + c]) f |= 4u;
        if (r < HH-1   && mf[EH + r*WW + c])     f |= 8u;
        flg[v] = (unsigned char)f;
        topo[v] = 0u;
    }
    __shared__ int s_cnt;
    if (tid == 0) {
        ord[0] = 0; par[0] = -1;
        g_lvl[tr][b*(NN+2)] = 0; g_lvl[tr][b*(NN+2)+1] = 1;
    }
    __syncthreads();

    int cur = 0, end = 1, d = 0;
    while (true) {
        if (tid == 0) s_cnt = 0;
        __syncthreads();
        for (int i = cur + tid; i < end; i += T) {
            int u = ord[i]; int pu = par[u];
            unsigned f = flg[u];
            int tmp[4]; int m = 0;
            if (f & 1u)  { int nb = u - 1;  if (nb != pu) tmp[m++] = nb; }
            if (f & 2u)  { int nb = u + 1;  if (nb != pu) tmp[m++] = nb; }
            if (f & 4u)  { int nb = u - WW; if (nb != pu) tmp[m++] = nb; }
            if (f & 8u)  { int nb = u + WW; if (nb != pu) tmp[m++] = nb; }
            int base = end + atomicAdd(&s_cnt, m);
            topo[i] |= ((unsigned)base << 14) | ((unsigned)m << 28);
            for (int j = 0; j < m; j++) {
                ord[base + j] = tmp[j];
                par[tmp[j]] = u;
                topo[base + j] = (unsigned)i;   // pp field; cs/cn filled next level
            }
        }
        __syncthreads();
        int cnt = s_cnt;
        if (tid == 0) g_lvl[tr][b*(NN+2) + d + 2] = end + cnt;
        if (cnt == 0) { if (tid == 0) g_nlev[tr][b] = d + 1; break; }
        cur = end; end += cnt; d++;
        __syncthreads();
    }
    __syncthreads();
    for (int v = tid; v < NN; v += T) {
        g_ord[tr][b*NN + v] = ord[v];
        g_par[tr][b*NN + v] = par[v];
        g_topo[tr][b*NN + v] = topo[v];
    }
}

// node weights (position-indexed). low: thread per position.
__global__ void k_nodew_low(const float* __restrict__ feat) {
    int i = blockIdx.x*blockDim.x + threadIdx.x;
    if (i >= BN*NN) return;
    int b = i / NN;
    int v = g_ord[0][i];
    int pu = g_par[0][b*NN + v];
    float wv = 0.0f;
    if (pu >= 0) {
        const float* f = feat + (size_t)b * CLOW * NN;
        float ss = 0.0f;
        #pragma unroll
        for (int c = 0; c < CLOW; c++) {
            float d = f[c*NN + v] - f[c*NN + pu];
            ss += d * d;
        }
        wv = expf(-ss / 0.02f);
    }
    g_wpos[0][i] = wv;
}

// high: warp per position, float4 loads from transposed feats.
__global__ __launch_bounds__(256) void k_nodew_high() {
    int w = (blockIdx.x*blockDim.x + threadIdx.x) >> 5;
    int lane = threadIdx.x & 31;
    if (w >= BN*NN) return;
    int b = w / NN;
    int v = g_ord[1][w];
    int pu = g_par[1][b*NN + v];
    float wv = 0.0f;
    if (pu >= 0) {
        const float4* fa = (const float4*)(g_hft + ((size_t)b*NN + v)*CHIGH);
        const float4* fb = (const float4*)(g_hft + ((size_t)b*NN + pu)*CHIGH);
        float ss = 0.0f;
        #pragma unroll
        for (int k = 0; k < 4; k++) {
            float4 x = fa[lane + 32*k];
            float4 y = fb[lane + 32*k];
            float d0 = x.x - y.x, d1 = x.y - y.y, d2 = x.z - y.z, d3 = x.w - y.w;
            ss += d0*d0 + d1*d1 + d2*d2 + d3*d3;
        }
        #pragma unroll
        for (int off = 16; off; off >>= 1) ss += __shfl_down_sync(0xffffffffu, ss, off);
        wv = expf(-ss);   // sigma = 1
    }
    if (lane == 0) g_wpos[1][w] = wv;
}

__global__ void k_invord1() {
    int i = blockIdx.x*blockDim.x + threadIdx.x;
    if (i < BN*NN) g_posN1[(i/NN)*NN + g_ord[1][i]] = i % NN;
}
__global__ void k_perm01() {
    int i = blockIdx.x*blockDim.x + threadIdx.x;
    if (i < BN*NN) g_perm01[i] = g_posN1[(i/NN)*NN + g_ord[0][i]];
}
// prob -> [b][c][pos0]
__global__ void k_permute0() {
    int i = blockIdx.x*blockDim.x + threadIdx.x;
    if (i >= BN*NN) return;
    int b = i / NN, p = i % NN;
    int u = g_ord[0][i];
    #pragma unroll
    for (int c = 0; c < NCH; c++)
        g_f0[((size_t)b*NCH + c)*NN + p] = g_prob[((size_t)b*NCH + c)*NN + u];
}

// Fused two-stage tree DP, all state in shared memory, small-level warp runs.
// Stage-1 block (b,g) reads exactly the g_f1 channels stage-0 block (b,g)
// wrote => inter-stage dependency is block-local (__syncthreads orders it).
__global__ __launch_bounds__(DP_T) void k_treedp() {
    int b = blockIdx.x / NGROUP, g = blockIdx.x % NGROUP;
    int tid = threadIdx.x;
    int nreal = (g == NGROUP-1) ? (NCH - 2*(NGROUP-1)) : 2;   // 2×10 + 1
    int cbase = g*2;
    int CH = nreal + 1;

    extern __shared__ char smraw2[];
    float* A      = (float*)smraw2;                  // 3*NN
    float* wv     = (float*)(smraw2 + 3*NN*4);       // NN
    unsigned* tp  = (unsigned*)(smraw2 + 4*NN*4);    // NN
    int* slvl     = (int*)(smraw2 + 5*NN*4);         // LVCAP

    for (int st = 0; st < 2; st++) {
        const int tr = st;
        const float* FP = (st == 0 ? g_f0 : g_f1) + (size_t)b*NCH*NN;
        int D = g_nlev[tr][b];

        for (int i = tid; i < NN; i += DP_T) {
            wv[i] = g_wpos[tr][b*NN + i];
            tp[i] = g_topo[tr][b*NN + i];
        }
        for (int i = tid; i < D + 1; i += DP_T) slvl[i] = g_lvl[tr][b*(NN+2) + i];
        for (int c = 0; c < nreal; c++)
            for (int i = tid; i < NN; i += DP_T) A[c*NN + i] = FP[(size_t)(cbase + c)*NN + i];
        for (int i = tid; i < NN; i += DP_T) A[nreal*NN + i] = 1.0f;
        __syncthreads();

        // up: children before parents
        {
            int d = D - 1;
            while (d >= 0) {
                int lo = slvl[d], cnt = slvl[d+1] - lo, m = cnt * CH;
                if (m > 32) {
                    for (int t = tid; t < m; t += DP_T) {
                        int c = t / cnt, i = lo + (t - c*cnt);
                        unsigned u = tp[i];
                        int cs = (u >> 14) & 0x3FFF, cn = u >> 28;
                        float acc = A[c*NN + i];
                        for (int j = cs; j < cs + cn; j++) acc += wv[j] * A[c*NN + j];
                        A[c*NN + i] = acc;
                    }
                    __syncthreads();
                    d--;
                } else {
                    // maximal run of small levels, processed by warp 0
                    int e = d;
                    while (e > 0 && (slvl[e] - slvl[e-1]) * CH <= 32) e--;
                    if (tid < 32) {
                        for (int dd = d; dd >= e; dd--) {
                            int lo2 = slvl[dd], cnt2 = slvl[dd+1] - lo2, m2 = cnt2 * CH;
                            if (tid < m2) {
                                int c = tid / cnt2, i = lo2 + (tid - c*cnt2);
                                unsigned u = tp[i];
                                int cs = (u >> 14) & 0x3FFF, cn = u >> 28;
                                float acc = A[c*NN + i];
                                for (int j = cs; j < cs + cn; j++) acc += wv[j] * A[c*NN + j];
                                A[c*NN + i] = acc;
                            }
                            __syncwarp();
                        }
                    }
                    __syncthreads();
                    d = e - 1;
                }
            }
        }
        // down: parents before children (root level identity)
        {
            int d = 1;
            while (d < D) {
                int lo = slvl[d], cnt = slvl[d+1] - lo, m = cnt * CH;
                if (m > 32) {
                    for (int t = tid; t < m; t += DP_T) {
                        int c = t / cnt, i = lo + (t - c*cnt);
                        int pp = tp[i] & 0x3FFF;
                        float av = A[c*NN + i];
                        float wu = wv[i];
                        A[c*NN + i] = av + wu * (A[c*NN + pp] - wu * av);
                    }
                    __syncthreads();
                    d++;
                } else {
                    int e = d;
                    while (e < D - 1 && (slvl[e+2] - slvl[e+1]) * CH <= 32) e++;
                    if (tid < 32) {
                        for (int dd = d; dd <= e; dd++) {
                            int lo2 = slvl[dd], cnt2 = slvl[dd+1] - lo2, m2 = cnt2 * CH;
                            if (tid < m2) {
                                int c = tid / cnt2, i = lo2 + (tid - c*cnt2);
                                int pp = tp[i] & 0x3FFF;
                                float av = A[c*NN + i];
                                float wu = wv[i];
                                A[c*NN + i] = av + wu * (A[c*NN + pp] - wu * av);
                            }
                            __syncwarp();
                        }
                    }
                    __syncthreads();
                    d = e + 1;
                }
            }
        }
        // normalize + write
        for (int t = tid; t < NN*nreal; t += DP_T) {
            int c = t / NN, i = t - c*NN;
            float val = A[c*NN + i] / A[nreal*NN + i];
            if (st == 0) {
                g_f1[((size_t)b*NCH + cbase + c)*NN + g_perm01[b*NN + i]] = val;
            } else {
                g_AS2[(size_t)b*NCH*NN + (size_t)(cbase + c)*NN + g_ord[1][b*NN + i]] = val;
            }
        }
        __syncthreads();
    }
}

__global__ void k_zero_acc() { g_acc[0] = 0.0; g_acc[1] = 0.0; }

__global__ __launch_bounds__(256) void k_loss(const float* __restrict__ roi) {
    double lsum = 0.0, nsum = 0.0;
    int stride = gridDim.x * blockDim.x;
    for (int idx = blockIdx.x*blockDim.x + threadIdx.x; idx < BN*NCH*NN; idx += stride) {
        int v = idx % NN;
        int bc = idx / NN;
        int c = bc % NCH, b = bc / NCH;
        int h = v / WW, wd = v % WW;
        float r = roi[b*(2*HH)*(2*WW) + (2*h)*(2*WW) + 2*wd];
        lsum += (double)(r * fabsf(g_prob[idx] - g_AS2[idx]));
        if (c == 0) nsum += (double)r;
    }
    __shared__ double shl[256], shn[256];
    int tid = threadIdx.x;
    shl[tid] = lsum; shn[tid] = nsum;
    __syncthreads();
    for (int off = 128; off > 0; off >>= 1) {
        if (tid < off) { shl[tid] += shl[tid+off]; shn[tid] += shn[tid+off]; }
        __syncthreads();
    }
    if (tid == 0) {
        atomicAdd(&g_acc[0], shl[0]);
        atomicAdd(&g_acc[1], shn[0]);
    }
}

__global__ void k_write(float* out) {
    double n = g_acc[1];
    out[0] = (n > 0.0) ? (float)(g_acc[0] / n) : 0.0f;
}

// ---------------- launch ----------------
extern "C" void kernel_launch(void* const* d_in, const int* in_sizes, int n_in,
                              void* d_out, int out_size) {
    const float *preds = nullptr, *lowf = nullptr, *highf = nullptr, *roi = nullptr;
    for (int i = 0; i < n_in; i++) {
        switch (in_sizes[i]) {
            case BN*NCH*NN:        preds = (const float*)d_in[i]; break;
            case BN*CLOW*NN:       lowf  = (const float*)d_in[i]; break;
            case BN*CHIGH*NN:      highf = (const float*)d_in[i]; break;
            case BN*(2*HH)*(2*WW): roi   = (const float*)d_in[i]; break;
        }
    }
    float* out = (float*)d_out;

    static int attr_done = 0;
    if (!attr_done) {
        cudaFuncSetAttribute(k_boruvka_both, cudaFuncAttributeMaxDynamicSharedMemorySize, SMEM_BORUVKA);
        cudaFuncSetAttribute(k_bfs_both,     cudaFuncAttributeMaxDynamicSharedMemorySize, BFS_SMEM);
        cudaFuncSetAttribute(k_treedp,       cudaFuncAttributeMaxDynamicSharedMemorySize, DP_SMEM);
        attr_done = 1;
    }

    k_sigmoid<<<(BN*NCH*NN + 255)/256, 256>>>(preds);
    k_transpose<<<dim3(NN/32, CHIGH/32, BN), dim3(32,32)>>>(highf);

    k_edgew_low <<<(BN*EE + 127)/128, 128>>>(lowf);
    k_edgew_high<<<(BN*EE*32 + 255)/256, 256>>>();

    k_boruvka_both<<<2*BN, 1024, SMEM_BORUVKA>>>();
    k_bfs_both<<<2*BN, 256, BFS_SMEM>>>();

    k_nodew_low <<<(BN*NN + 127)/128, 128>>>(lowf);
    k_nodew_high<<<(BN*NN*32 + 255)/256, 256>>>();

    k_invord1 <<<(BN*NN + 255)/256, 256>>>();
    k_perm01  <<<(BN*NN + 255)/256, 256>>>();
    k_permute0<<<(BN*NN + 255)/256, 256>>>();

    k_treedp<<<BN*NGROUP, DP_T, DP_SMEM>>>();

    k_zero_acc<<<1, 1>>>();
    k_loss<<<1024, 256>>>(roi);
    k_write<<<1, 1>>>(out);
    (void)out_size;
}